// round 7
// baseline (speedup 1.0000x reference)
#include <cuda_runtime.h>
#include <cuda_bf16.h>
#include <cstdint>

// Problem constants
#define B_DIM   2048
#define P_DIM   50
#define K_DIM   28672            // 512*7*8
#define NP      56               // P padded to 56 (7 n8-tiles)
#define KS      28               // K splits (uniform NITER=32, grid 448)
#define KCHUNK  (K_DIM / KS)     // 1024
#define KB      32               // K floats per pipeline stage
#define NITER   (KCHUNK / KB)    // 32
#define MT      128              // M tile
#define MTILES  (B_DIM / MT)     // 16
#define STAGES  3

// Swizzled tiles: exact 128B rows, XOR granule swizzle -> conflict-free
#define AS_BYTES (MT * KB * 4)               // 16384
#define BS_BYTES (NP * KB * 4)               // 7168
#define STAGE_BYTES (AS_BYTES + BS_BYTES)    // 23552
#define SMEM_BYTES (STAGES * STAGE_BYTES)    // 70656  (< 72KB -> 3 CTAs/SM)

// Static device scratch (allocation-free rule)
__device__ __nv_bfloat16 g_xp[(size_t)KS * MTILES * MT * NP];   // 6.4 MB (bf16)
__device__ float g_x2[(size_t)KS * B_DIM];                       // 229 KB
__device__ float g_p2p[KS][NP];                                  // p2 partials per ks

// ---------------------------------------------------------------------------
__device__ __forceinline__ void cpa16(uint32_t saddr, const void* gaddr) {
    asm volatile("cp.async.cg.shared.global [%0], [%1], 16;\n"
                 :: "r"(saddr), "l"(gaddr));
}
// zero-fill variant: src-size=0 reads nothing, fills 16B of zeros
__device__ __forceinline__ void cpa16z(uint32_t saddr, const void* gaddr, int srcsz) {
    asm volatile("cp.async.cg.shared.global [%0], [%1], 16, %2;\n"
                 :: "r"(saddr), "l"(gaddr), "r"(srcsz));
}
__device__ __forceinline__ void cpa_commit() {
    asm volatile("cp.async.commit_group;\n" ::: "memory");
}
__device__ __forceinline__ void cpa_wait2() {
    asm volatile("cp.async.wait_group 2;\n" ::: "memory");
}
__device__ __forceinline__ uint32_t pack_bf16x2(float2 v) {
    __nv_bfloat162 h = __floats2bfloat162_rn(v.x, v.y);
    return *(uint32_t*)&h;
}

// ---------------------------------------------------------------------------
// Fused GEMM: x fp32 + proto fp32 staged via cp.async (3 stages, XOR swizzle),
// in-register bf16 convert, x^2 (all blocks) and p^2 (mt==0 blocks) fused.
// grid (MTILES, KS) = 448 blocks, 256 threads = 8 warps.
// Iteration skeleton (RACE-SAFE): sync -> issue(it+2) -> wait2 -> sync -> compute
// (wait_group only fences the issuing thread's copies; the post-wait barrier
//  is REQUIRED before reading other threads' cp.async data.)
// ---------------------------------------------------------------------------
__global__ void __launch_bounds__(256, 3) gemm_kernel(
        const float* __restrict__ x, const float* __restrict__ proto) {
    extern __shared__ char smem[];

    const int mt   = blockIdx.x;
    const int ks   = blockIdx.y;
    const int t    = threadIdx.x;
    const int warp = t >> 5;
    const int lane = t & 31;
    const int q    = lane & 3;
    const int rr   = lane >> 2;       // 0..7
    const int b0   = mt * MT;
    const int k0   = ks * KCHUNK;

    // --- cp.async mappings ---
    // A: thread -> (row xrr + 32*pass, 16B granule xch); swizzled slot
    const int xrr = t >> 3;           // 0..31
    const int xch = t & 7;            // granule 0..7 (row = 8 granules = 128B)
    const float* xg0 = x + (size_t)(b0 + xrr) * K_DIM + k0 + xch * 4;
    const uint32_t a_sw = (uint32_t)(xch ^ ((xrr & 3) << 1));

    // B: thread -> (row prr, granules pch and pch+4); rows >= P_DIM zero-filled
    const int prr = t >> 2;           // 0..63 (only < NP participate)
    const int pch = t & 3;
    const float* pg0 = proto + (size_t)prr * K_DIM + k0 + pch * 4;
    const uint32_t b_sw0 = (uint32_t)( pch      ^ ((prr & 3) << 1));
    const uint32_t b_sw1 = (uint32_t)((pch + 4) ^ ((prr & 3) << 1));
    const int psz = (prr < P_DIM) ? 16 : 0;

    const uint32_t smem_u = (uint32_t)__cvta_generic_to_shared(smem);

    auto issue = [&](int stage, int chunk) {
        const uint32_t sb = smem_u + (uint32_t)(stage * STAGE_BYTES);
        const float* xg = xg0 + chunk * KB;
        #pragma unroll
        for (int pass = 0; pass < 4; pass++) {
            cpa16(sb + (uint32_t)((xrr + pass * 32) * 128) + (a_sw << 4),
                  xg + (size_t)(pass * 32) * K_DIM);
        }
        if (prr < NP) {
            const float* pg = pg0 + chunk * KB;
            const uint32_t bb = sb + AS_BYTES + (uint32_t)(prr * 128);
            cpa16z(bb + (b_sw0 << 4), pg,      psz);
            cpa16z(bb + (b_sw1 << 4), pg + 16, psz);
        }
        cpa_commit();
    };

    // prologue
    issue(0, 0);
    issue(1, 1);

    // fragment rows
    const int r0 = warp * 16 + rr;
    const int r1 = r0 + 8;
    const uint32_t swf = (uint32_t)((rr & 3) << 1);   // r0&3 == rr&3 (warp*16 % 4 == 0)
    const int qg = q >> 1;                            // granule select within k16
    const int qp = (q & 1) << 3;                      // float2 byte offset in granule

    float acc[7][4];
    #pragma unroll
    for (int j = 0; j < 7; j++)
        #pragma unroll
        for (int c = 0; c < 4; c++) acc[j][c] = 0.f;
    float x2a = 0.f, x2b = 0.f;
    float p2a[7];
    #pragma unroll
    for (int j = 0; j < 7; j++) p2a[j] = 0.f;

    int stage = 0;
    for (int it = 0; it < NITER; ++it) {
        __syncthreads();                 // all warps done computing it-1 -> stage (it+2)%3 free
        const int nxt = it + 2;
        if (nxt < NITER) issue((stage + 2 >= STAGES) ? stage + 2 - STAGES : stage + 2, nxt);
        else             cpa_commit();   // keep group counting uniform
        cpa_wait2();                     // my copies for chunk `it` complete
        __syncthreads();                 // ALL threads' copies for chunk `it` visible

        const char* sb = smem + stage * STAGE_BYTES;
        const char* bbase = sb + AS_BYTES;
        if (++stage == STAGES) stage = 0;

        #pragma unroll
        for (int kk = 0; kk < 2; ++kk) {
            const uint32_t g0 = (uint32_t)(kk * 4 + qg);
            const uint32_t o_lo = ((g0 ^ swf) << 4) + qp;         // cols kb..kb+1
            const uint32_t o_hi = (((g0 + 2) ^ swf) << 4) + qp;   // cols kb+8..kb+9
            float2 a00 = *(const float2*)(sb + r0 * 128 + o_lo);
            float2 a01 = *(const float2*)(sb + r0 * 128 + o_hi);
            float2 a10 = *(const float2*)(sb + r1 * 128 + o_lo);
            float2 a11 = *(const float2*)(sb + r1 * 128 + o_hi);
            x2a += a00.x * a00.x + a00.y * a00.y + a01.x * a01.x + a01.y * a01.y;
            x2b += a10.x * a10.x + a10.y * a10.y + a11.x * a11.x + a11.y * a11.y;
            uint32_t A0 = pack_bf16x2(a00);
            uint32_t A1 = pack_bf16x2(a10);
            uint32_t A2 = pack_bf16x2(a01);
            uint32_t A3 = pack_bf16x2(a11);
            #pragma unroll
            for (int j = 0; j < 7; j++) {
                const int n = j * 8 + rr;                 // n&3 == rr&3 -> same swf
                const char* brow = bbase + n * 128;
                float2 b0 = *(const float2*)(brow + o_lo);
                float2 b1 = *(const float2*)(brow + o_hi);
                if (mt == 0)
                    p2a[j] += b0.x * b0.x + b0.y * b0.y + b1.x * b1.x + b1.y * b1.y;
                uint32_t B0 = pack_bf16x2(b0);
                uint32_t B1 = pack_bf16x2(b1);
                asm volatile(
                    "mma.sync.aligned.m16n8k16.row.col.f32.bf16.bf16.f32 "
                    "{%0,%1,%2,%3}, {%4,%5,%6,%7}, {%8,%9}, {%0,%1,%2,%3};\n"
                    : "+f"(acc[j][0]), "+f"(acc[j][1]), "+f"(acc[j][2]), "+f"(acc[j][3])
                    : "r"(A0), "r"(A1), "r"(A2), "r"(A3), "r"(B0), "r"(B1));
            }
        }
    }

    // xp partials in bf16 (private scratch slice per block — deterministic)
    __nv_bfloat16* outp = g_xp + ((size_t)ks * MTILES + mt) * (MT * NP);
    const int ccol = q * 2;
    #pragma unroll
    for (int j = 0; j < 7; j++) {
        const int n = j * 8 + ccol;
        *(uint32_t*)&outp[(size_t)r0 * NP + n] = pack_bf16x2(make_float2(acc[j][0], acc[j][1]));
        *(uint32_t*)&outp[(size_t)r1 * NP + n] = pack_bf16x2(make_float2(acc[j][2], acc[j][3]));
    }

    // x^2 partials: quad reduce (lanes differ only in k coverage)
    x2a += __shfl_xor_sync(0xffffffffu, x2a, 1);
    x2a += __shfl_xor_sync(0xffffffffu, x2a, 2);
    x2b += __shfl_xor_sync(0xffffffffu, x2b, 1);
    x2b += __shfl_xor_sync(0xffffffffu, x2b, 2);
    if (q == 0) {
        g_x2[(size_t)ks * B_DIM + b0 + r0] = x2a;
        g_x2[(size_t)ks * B_DIM + b0 + r1] = x2b;
    }

    // p^2 partials for this k-chunk (identical in every warp; warp 0 writes)
    if (mt == 0 && warp == 0) {
        #pragma unroll
        for (int j = 0; j < 7; j++) {
            float s = p2a[j];
            s += __shfl_xor_sync(0xffffffffu, s, 1);
            s += __shfl_xor_sync(0xffffffffu, s, 2);
            if (q == 0) g_p2p[ks][j * 8 + rr] = s;
        }
    }
}

// ---------------------------------------------------------------------------
// Epilogue: reduce split-K partials, relu(x2 + p2 - 2*xp)
// ---------------------------------------------------------------------------
__global__ void __launch_bounds__(64) epilogue_kernel(float* __restrict__ out) {
    const int b = blockIdx.x;
    const int p = threadIdx.x;   // 0..63
    const int mt = b >> 7, r = b & 127;

    float xp = 0.f;
    if (p < NP) {
        #pragma unroll
        for (int ks = 0; ks < KS; ++ks)
            xp += __bfloat162float(
                g_xp[((size_t)ks * MTILES + mt) * (MT * NP) + (size_t)r * NP + p]);
    }

    __shared__ float x2sh;
    if (p < 32) {
        float s = (p < KS) ? g_x2[(size_t)p * B_DIM + b] : 0.f;
        #pragma unroll
        for (int off = 16; off > 0; off >>= 1)
            s += __shfl_xor_sync(0xffffffffu, s, off);
        if (p == 0) x2sh = s;
    }
    __syncthreads();

    if (p < P_DIM) {
        float p2 = 0.f;
        #pragma unroll
        for (int ks = 0; ks < KS; ++ks) p2 += g_p2p[ks][p];
        float d = x2sh + p2 - 2.f * xp;
        out[(size_t)b * P_DIM + p] = d > 0.f ? d : 0.f;
    }
}

// ---------------------------------------------------------------------------
extern "C" void kernel_launch(void* const* d_in, const int* in_sizes, int n_in,
                              void* d_out, int out_size) {
    const float* x     = (const float*)d_in[0];
    const float* proto = (const float*)d_in[1];
    if (in_sizes[0] == P_DIM * K_DIM) {  // defensive: swap if order differs
        x     = (const float*)d_in[1];
        proto = (const float*)d_in[0];
    }
    float* out = (float*)d_out;

    cudaFuncSetAttribute(gemm_kernel,
                         cudaFuncAttributeMaxDynamicSharedMemorySize, SMEM_BYTES);

    gemm_kernel<<<dim3(MTILES, KS), 256, SMEM_BYTES>>>(x, proto);
    epilogue_kernel<<<B_DIM, 64>>>(out);
}

// round 8
// speedup vs baseline: 1.0338x; 1.0338x over previous
#include <cuda_runtime.h>
#include <cuda_bf16.h>
#include <cstdint>

// Problem constants
#define B_DIM   2048
#define P_DIM   50
#define K_DIM   28672            // 512*7*8
#define NP      56               // P padded to 56 (7 n8-tiles)
#define KS      28               // K splits (uniform NITER=32, grid 448)
#define KCHUNK  (K_DIM / KS)     // 1024
#define KB      32               // K floats per pipeline stage
#define NITER   (KCHUNK / KB)    // 32
#define MT      128              // M tile
#define MTILES  (B_DIM / MT)     // 16
#define STAGES  3

// Swizzled tiles: exact 128B rows, XOR granule swizzle -> conflict-free
#define AS_BYTES (MT * KB * 4)               // 16384
#define BS_BYTES (NP * KB * 4)               // 7168
#define STAGE_BYTES (AS_BYTES + BS_BYTES)    // 23552
#define SMEM_BYTES (STAGES * STAGE_BYTES)    // 70656  (< 72KB -> 3 CTAs/SM)

// Static device scratch (allocation-free rule)
__device__ __nv_bfloat16 g_xp[(size_t)KS * MTILES * MT * NP];   // 6.4 MB (bf16)
__device__ float g_x2[(size_t)KS * B_DIM];                       // 229 KB
__device__ float g_p2p[KS][NP];                                  // p2 partials per ks

// ---------------------------------------------------------------------------
__device__ __forceinline__ void cpa16(uint32_t saddr, const void* gaddr) {
    asm volatile("cp.async.cg.shared.global [%0], [%1], 16;\n"
                 :: "r"(saddr), "l"(gaddr));
}
// zero-fill variant: src-size=0 reads nothing, fills 16B of zeros
__device__ __forceinline__ void cpa16z(uint32_t saddr, const void* gaddr, int srcsz) {
    asm volatile("cp.async.cg.shared.global [%0], [%1], 16, %2;\n"
                 :: "r"(saddr), "l"(gaddr), "r"(srcsz));
}
__device__ __forceinline__ void cpa_commit() {
    asm volatile("cp.async.commit_group;\n" ::: "memory");
}
__device__ __forceinline__ void cpa_wait2() {
    asm volatile("cp.async.wait_group 2;\n" ::: "memory");
}
__device__ __forceinline__ uint32_t pack_bf16x2(float2 v) {
    __nv_bfloat162 h = __floats2bfloat162_rn(v.x, v.y);
    return *(uint32_t*)&h;
}

// ---------------------------------------------------------------------------
// Fused GEMM: x fp32 + proto fp32 staged via cp.async (3 stages, XOR swizzle),
// in-register bf16 convert, x^2 (all blocks) and p^2 (mt==0 blocks) fused.
// grid (MTILES, KS) = 448 blocks, 256 threads = 8 warps.
// Iteration skeleton (RACE-SAFE): sync -> issue(it+2) -> wait2 -> sync -> compute
// (wait_group only fences the issuing thread's copies; the post-wait barrier
//  is REQUIRED before reading other threads' cp.async data.)
// ---------------------------------------------------------------------------
__global__ void __launch_bounds__(256, 3) gemm_kernel(
        const float* __restrict__ x, const float* __restrict__ proto) {
    extern __shared__ char smem[];

    const int mt   = blockIdx.x;
    const int ks   = blockIdx.y;
    const int t    = threadIdx.x;
    const int warp = t >> 5;
    const int lane = t & 31;
    const int q    = lane & 3;
    const int rr   = lane >> 2;       // 0..7
    const int b0   = mt * MT;
    const int k0   = ks * KCHUNK;

    // --- cp.async mappings ---
    // A: thread -> (row xrr + 32*pass, 16B granule xch); swizzled slot
    const int xrr = t >> 3;           // 0..31
    const int xch = t & 7;            // granule 0..7 (row = 8 granules = 128B)
    const float* xg0 = x + (size_t)(b0 + xrr) * K_DIM + k0 + xch * 4;
    const uint32_t a_sw = (uint32_t)(xch ^ ((xrr & 3) << 1));

    // B: thread -> (row prr, granules pch and pch+4); rows >= P_DIM zero-filled
    const int prr = t >> 2;           // 0..63 (only < NP participate)
    const int pch = t & 3;
    const float* pg0 = proto + (size_t)prr * K_DIM + k0 + pch * 4;
    const uint32_t b_sw0 = (uint32_t)( pch      ^ ((prr & 3) << 1));
    const uint32_t b_sw1 = (uint32_t)((pch + 4) ^ ((prr & 3) << 1));
    const int psz = (prr < P_DIM) ? 16 : 0;

    const uint32_t smem_u = (uint32_t)__cvta_generic_to_shared(smem);

    auto issue = [&](int stage, int chunk) {
        const uint32_t sb = smem_u + (uint32_t)(stage * STAGE_BYTES);
        const float* xg = xg0 + chunk * KB;
        #pragma unroll
        for (int pass = 0; pass < 4; pass++) {
            cpa16(sb + (uint32_t)((xrr + pass * 32) * 128) + (a_sw << 4),
                  xg + (size_t)(pass * 32) * K_DIM);
        }
        if (prr < NP) {
            const float* pg = pg0 + chunk * KB;
            const uint32_t bb = sb + AS_BYTES + (uint32_t)(prr * 128);
            cpa16z(bb + (b_sw0 << 4), pg,      psz);
            cpa16z(bb + (b_sw1 << 4), pg + 16, psz);
        }
        cpa_commit();
    };

    // prologue
    issue(0, 0);
    issue(1, 1);

    // fragment rows
    const int r0 = warp * 16 + rr;
    const int r1 = r0 + 8;
    const uint32_t swf = (uint32_t)((rr & 3) << 1);   // r0&3 == rr&3 (warp*16 % 4 == 0)
    const int qg = q >> 1;                            // granule select within k16
    const int qp = (q & 1) << 3;                      // float2 byte offset in granule

    float acc[7][4];
    #pragma unroll
    for (int j = 0; j < 7; j++)
        #pragma unroll
        for (int c = 0; c < 4; c++) acc[j][c] = 0.f;
    float x2a = 0.f, x2b = 0.f;
    float p2a[7];
    #pragma unroll
    for (int j = 0; j < 7; j++) p2a[j] = 0.f;

    int stage = 0;
    for (int it = 0; it < NITER; ++it) {
        __syncthreads();                 // all warps done computing it-1 -> stage (it+2)%3 free
        const int nxt = it + 2;
        if (nxt < NITER) issue((stage + 2 >= STAGES) ? stage + 2 - STAGES : stage + 2, nxt);
        else             cpa_commit();   // keep group counting uniform
        cpa_wait2();                     // my copies for chunk `it` complete
        __syncthreads();                 // ALL threads' copies for chunk `it` visible

        const char* sb = smem + stage * STAGE_BYTES;
        const char* bbase = sb + AS_BYTES;
        if (++stage == STAGES) stage = 0;

        #pragma unroll
        for (int kk = 0; kk < 2; ++kk) {
            const uint32_t g0 = (uint32_t)(kk * 4 + qg);
            const uint32_t o_lo = ((g0 ^ swf) << 4) + qp;         // cols kb..kb+1
            const uint32_t o_hi = (((g0 + 2) ^ swf) << 4) + qp;   // cols kb+8..kb+9
            float2 a00 = *(const float2*)(sb + r0 * 128 + o_lo);
            float2 a01 = *(const float2*)(sb + r0 * 128 + o_hi);
            float2 a10 = *(const float2*)(sb + r1 * 128 + o_lo);
            float2 a11 = *(const float2*)(sb + r1 * 128 + o_hi);
            x2a += a00.x * a00.x + a00.y * a00.y + a01.x * a01.x + a01.y * a01.y;
            x2b += a10.x * a10.x + a10.y * a10.y + a11.x * a11.x + a11.y * a11.y;
            uint32_t A0 = pack_bf16x2(a00);
            uint32_t A1 = pack_bf16x2(a10);
            uint32_t A2 = pack_bf16x2(a01);
            uint32_t A3 = pack_bf16x2(a11);
            #pragma unroll
            for (int j = 0; j < 7; j++) {
                const int n = j * 8 + rr;                 // n&3 == rr&3 -> same swf
                const char* brow = bbase + n * 128;
                float2 b0 = *(const float2*)(brow + o_lo);
                float2 b1 = *(const float2*)(brow + o_hi);
                if (mt == 0)
                    p2a[j] += b0.x * b0.x + b0.y * b0.y + b1.x * b1.x + b1.y * b1.y;
                uint32_t B0 = pack_bf16x2(b0);
                uint32_t B1 = pack_bf16x2(b1);
                asm volatile(
                    "mma.sync.aligned.m16n8k16.row.col.f32.bf16.bf16.f32 "
                    "{%0,%1,%2,%3}, {%4,%5,%6,%7}, {%8,%9}, {%0,%1,%2,%3};\n"
                    : "+f"(acc[j][0]), "+f"(acc[j][1]), "+f"(acc[j][2]), "+f"(acc[j][3])
                    : "r"(A0), "r"(A1), "r"(A2), "r"(A3), "r"(B0), "r"(B1));
            }
        }
    }

    // xp partials in bf16 (private scratch slice per block — deterministic)
    __nv_bfloat16* outp = g_xp + ((size_t)ks * MTILES + mt) * (MT * NP);
    const int ccol = q * 2;
    #pragma unroll
    for (int j = 0; j < 7; j++) {
        const int n = j * 8 + ccol;
        *(uint32_t*)&outp[(size_t)r0 * NP + n] = pack_bf16x2(make_float2(acc[j][0], acc[j][1]));
        *(uint32_t*)&outp[(size_t)r1 * NP + n] = pack_bf16x2(make_float2(acc[j][2], acc[j][3]));
    }

    // x^2 partials: quad reduce (lanes differ only in k coverage)
    x2a += __shfl_xor_sync(0xffffffffu, x2a, 1);
    x2a += __shfl_xor_sync(0xffffffffu, x2a, 2);
    x2b += __shfl_xor_sync(0xffffffffu, x2b, 1);
    x2b += __shfl_xor_sync(0xffffffffu, x2b, 2);
    if (q == 0) {
        g_x2[(size_t)ks * B_DIM + b0 + r0] = x2a;
        g_x2[(size_t)ks * B_DIM + b0 + r1] = x2b;
    }

    // p^2 partials for this k-chunk (identical in every warp; warp 0 writes)
    if (mt == 0 && warp == 0) {
        #pragma unroll
        for (int j = 0; j < 7; j++) {
            float s = p2a[j];
            s += __shfl_xor_sync(0xffffffffu, s, 1);
            s += __shfl_xor_sync(0xffffffffu, s, 2);
            if (q == 0) g_p2p[ks][j * 8 + rr] = s;
        }
    }
}

// ---------------------------------------------------------------------------
// Epilogue: reduce split-K partials, relu(x2 + p2 - 2*xp)
// ---------------------------------------------------------------------------
__global__ void __launch_bounds__(64) epilogue_kernel(float* __restrict__ out) {
    const int b = blockIdx.x;
    const int p = threadIdx.x;   // 0..63
    const int mt = b >> 7, r = b & 127;

    float xp = 0.f;
    if (p < NP) {
        #pragma unroll
        for (int ks = 0; ks < KS; ++ks)
            xp += __bfloat162float(
                g_xp[((size_t)ks * MTILES + mt) * (MT * NP) + (size_t)r * NP + p]);
    }

    __shared__ float x2sh;
    if (p < 32) {
        float s = (p < KS) ? g_x2[(size_t)p * B_DIM + b] : 0.f;
        #pragma unroll
        for (int off = 16; off > 0; off >>= 1)
            s += __shfl_xor_sync(0xffffffffu, s, off);
        if (p == 0) x2sh = s;
    }
    __syncthreads();

    if (p < P_DIM) {
        float p2 = 0.f;
        #pragma unroll
        for (int ks = 0; ks < KS; ++ks) p2 += g_p2p[ks][p];
        float d = x2sh + p2 - 2.f * xp;
        out[(size_t)b * P_DIM + p] = d > 0.f ? d : 0.f;
    }
}

// ---------------------------------------------------------------------------
extern "C" void kernel_launch(void* const* d_in, const int* in_sizes, int n_in,
                              void* d_out, int out_size) {
    const float* x     = (const float*)d_in[0];
    const float* proto = (const float*)d_in[1];
    if (in_sizes[0] == P_DIM * K_DIM) {  // defensive: swap if order differs
        x     = (const float*)d_in[1];
        proto = (const float*)d_in[0];
    }
    float* out = (float*)d_out;

    cudaFuncSetAttribute(gemm_kernel,
                         cudaFuncAttributeMaxDynamicSharedMemorySize, SMEM_BYTES);

    gemm_kernel<<<dim3(MTILES, KS), 256, SMEM_BYTES>>>(x, proto);
    epilogue_kernel<<<B_DIM, 64>>>(out);
}